// round 2
// baseline (speedup 1.0000x reference)
#include <cuda_runtime.h>

// Eq3NetMini: B=8, N=48, EMBED=32, IN_DIM=33, N_OPS=8, HID=32
//
// y[b,h,i,j,k] = sum_d A[h,d]*x_j,d*x_k,d + R[h,j] + C[h,k] + base[h]
// with all x-means folded analytically (no (B,d,n,n,n) tensor materialized).
// One block per (b,i); relu-sum reduced per block, tiny finalize kernel.

#define NB 8
#define NN 48
#define ND 33
#define NH 32
#define NTHREADS 192

__device__ float g_partial[NB * NN * NH];   // per-(b,i) relu-sum over (j,k) per h

__global__ __launch_bounds__(NTHREADS, 3) void eq3_main(
    const int*   __restrict__ xcat,
    const float* __restrict__ xfeat,
    const float* __restrict__ embed,
    const float* __restrict__ coefs,     // (33, 8, 32) row-major: [d*256 + s*32 + h]
    const float* __restrict__ eq_bias)
{
    __shared__ float x_sm[NN * ND];      // x[b, row, d]
    __shared__ float s_sm[ND];           // mean over rows
    __shared__ float base_sm[NH];
    __shared__ float A_sm[ND * NH];      // [d*32 + h]
    __shared__ float B_sm[ND * NH];      // coef combo for R
    __shared__ float D_sm[ND * NH];      // coef combo for C
    __shared__ float R_sm[NH * NN];      // [h*48 + j]  (includes base)
    __shared__ float C_sm[NH * NN];      // [h*48 + k]
    __shared__ float part_sm[6][NH];

    const int t = threadIdx.x;
    const int b = blockIdx.y;
    const int i = blockIdx.x;

    // ---- load x (embed gather + xfeat concat) ----
    for (int e = t; e < NN * ND; e += NTHREADS) {
        int row = e / ND;
        int d   = e - row * ND;
        x_sm[e] = (d < 32) ? embed[xcat[b * NN + row] * 32 + d]
                           : xfeat[b * NN + row];
    }
    __syncthreads();

    // ---- column means s_d ----
    if (t < ND) {
        float su = 0.f;
        #pragma unroll 8
        for (int r = 0; r < NN; r++) su += x_sm[r * ND + t];
        s_sm[t] = su * (1.0f / 48.0f);
    }
    __syncthreads();

    // ---- per-block coefficient combos ----
    for (int e = t; e < ND * NH; e += NTHREADS) {
        int d = e >> 5;
        int h = e & 31;
        float xi = x_sm[i * ND + d];
        float s  = s_sm[d];
        const float* c = coefs + d * 256 + h;
        A_sm[e] = c[0]  * xi + c[32]  * s;            // op0 + op1
        B_sm[e] = (c[96] * xi + c[160] * s) * s;      // op3 + op5  -> R (j)
        D_sm[e] = (c[64] * xi + c[128] * s) * s;      // op2 + op4  -> C (k)
    }
    if (t < NH) {
        float acc = eq_bias[t];
        for (int d = 0; d < ND; d++) {
            float xi = x_sm[i * ND + d];
            float s  = s_sm[d];
            const float* c = coefs + d * 256 + t;
            acc += (c[192] * xi + c[224] * s) * s * s;  // op6 + op7
        }
        base_sm[t] = acc;
    }
    __syncthreads();

    // ---- R[h,j] (with base folded) and C[h,k] ----
    for (int e = t; e < NH * NN; e += NTHREADS) {
        int h = e / NN;
        int j = e - h * NN;
        float r  = base_sm[h];
        float cc = 0.f;
        for (int d = 0; d < ND; d++) {
            float xv = x_sm[j * ND + d];
            r  = fmaf(B_sm[d * NH + h], xv, r);
            cc = fmaf(D_sm[d * NH + h], xv, cc);
        }
        R_sm[e] = r;
        C_sm[e] = cc;
    }
    __syncthreads();

    // ---- main: per thread tile = (1 j) x (6 k) x (8 h), 2 tiles, 4 h-chunks ----
    const int lane = t & 31;
    const int warp = t >> 5;

    for (int hc = 0; hc < 4; hc++) {
        float pool[8];
        #pragma unroll
        for (int hh = 0; hh < 8; hh++) pool[hh] = 0.f;

        for (int tile = 0; tile < 2; tile++) {
            int p  = t + NTHREADS * tile;       // 0..383
            int j  = p >> 3;                    // 0..47
            int k0 = (p & 7) * 6;               // 0,6,...,42
            const float* xjp = x_sm + j * ND;
            const float* xkp = x_sm + k0 * ND;
            const float* Ap  = A_sm + hc * 8;
            const float* Rp  = R_sm + hc * 8 * NN;
            const float* Cp  = C_sm + hc * 8 * NN;

            float acc[8][6];
            #pragma unroll
            for (int hh = 0; hh < 8; hh++) {
                float rv = Rp[hh * NN + j];
                #pragma unroll
                for (int kk = 0; kk < 6; kk++)
                    acc[hh][kk] = rv + Cp[hh * NN + k0 + kk];
            }

            #pragma unroll 3
            for (int d = 0; d < ND; d++) {
                float xj = xjp[d];
                float pp[6];
                #pragma unroll
                for (int kk = 0; kk < 6; kk++)
                    pp[kk] = xj * xkp[kk * ND + d];
                #pragma unroll
                for (int hh = 0; hh < 8; hh++) {
                    float a = Ap[d * NH + hh];   // warp-uniform broadcast
                    #pragma unroll
                    for (int kk = 0; kk < 6; kk++)
                        acc[hh][kk] = fmaf(a, pp[kk], acc[hh][kk]);
                }
            }

            #pragma unroll
            for (int hh = 0; hh < 8; hh++) {
                float ss = 0.f;
                #pragma unroll
                for (int kk = 0; kk < 6; kk++)
                    ss += fmaxf(acc[hh][kk], 0.f);
                pool[hh] += ss;
            }
        }

        // warp reduce each pool[hh], lane 0 stages to smem
        #pragma unroll
        for (int hh = 0; hh < 8; hh++) {
            float v = pool[hh];
            #pragma unroll
            for (int off = 16; off; off >>= 1)
                v += __shfl_xor_sync(0xffffffffu, v, off);
            if (lane == 0) part_sm[warp][hc * 8 + hh] = v;
        }
    }
    __syncthreads();

    if (t < NH) {
        float su = 0.f;
        #pragma unroll
        for (int w = 0; w < 6; w++) su += part_sm[w][t];
        g_partial[(b * NN + i) * NH + t] = su;
    }
}

__global__ __launch_bounds__(256) void eq3_final(
    const float* __restrict__ out_w,
    const float* __restrict__ out_b,
    float*       __restrict__ out)
{
    const int b = threadIdx.x >> 5;   // 8 warps = 8 batch rows
    const int h = threadIdx.x & 31;
    float P = 0.f;
    #pragma unroll 8
    for (int i = 0; i < NN; i++)
        P += g_partial[(b * NN + i) * NH + h];
    P *= (1.0f / 110592.0f);          // mean over n^3
    P = fmaxf(P, 0.f);                // second relu (no-op but exact)
    float v = P * out_w[h];
    #pragma unroll
    for (int off = 16; off; off >>= 1)
        v += __shfl_xor_sync(0xffffffffu, v, off);
    if (h == 0) out[b] = v + out_b[0];
}

extern "C" void kernel_launch(void* const* d_in, const int* in_sizes, int n_in,
                              void* d_out, int out_size)
{
    const int*   xcat    = (const int*)  d_in[0];
    const float* xfeat   = (const float*)d_in[1];
    const float* embed   = (const float*)d_in[2];
    const float* coefs   = (const float*)d_in[3];
    const float* eq_bias = (const float*)d_in[4];
    const float* out_w   = (const float*)d_in[5];
    const float* out_b   = (const float*)d_in[6];
    float* out = (float*)d_out;

    dim3 grid(NN, NB);   // (i, b)
    eq3_main<<<grid, NTHREADS>>>(xcat, xfeat, embed, coefs, eq_bias);
    eq3_final<<<1, 256>>>(out_w, out_b, out);
}

// round 7
// speedup vs baseline: 1.1744x; 1.1744x over previous
#include <cuda_runtime.h>

// Eq3NetMini: B=8, N=48, EMBED=32, IN_DIM=33, N_OPS=8, HID=32
// y[b,h,i,j,k] = sum_d A[h,d]*x_j,d*x_k,d + R[h,j] + C[h,k] + base[h]
// Main loop uses packed fma.rn.f32x2 (FFMA2) with pack-free shared layouts.
// R5 fix: __align__(16) on all vector-loaded shared arrays (LDS.64/.128
// require aligned addresses; plain float arrays are only 4B-aligned).

#define NB 8
#define NN 48
#define ND 33
#define NH 32
#define NTHREADS 192

typedef unsigned long long u64;

__device__ __forceinline__ u64 pack2(float lo, float hi) {
    u64 r; asm("mov.b64 %0,{%1,%2};" : "=l"(r) : "f"(lo), "f"(hi)); return r;
}
__device__ __forceinline__ void unpack2(u64 v, float& lo, float& hi) {
    asm("mov.b64 {%0,%1},%2;" : "=f"(lo), "=f"(hi) : "l"(v));
}
__device__ __forceinline__ u64 fma2(u64 a, u64 b, u64 c) {
    u64 r; asm("fma.rn.f32x2 %0,%1,%2,%3;" : "=l"(r) : "l"(a), "l"(b), "l"(c)); return r;
}
__device__ __forceinline__ u64 mul2(u64 a, u64 b) {
    u64 r; asm("mul.rn.f32x2 %0,%1,%2;" : "=l"(r) : "l"(a), "l"(b)); return r;
}
__device__ __forceinline__ u64 add2(u64 a, u64 b) {
    u64 r; asm("add.rn.f32x2 %0,%1,%2;" : "=l"(r) : "l"(a), "l"(b)); return r;
}

__device__ float g_partial[NB * NN * NH];   // per-(b,i) relu-sum over (j,k) per h

__global__ __launch_bounds__(NTHREADS, 3) void eq3_main(
    const int*   __restrict__ xcat,
    const float* __restrict__ xfeat,
    const float* __restrict__ embed,
    const float* __restrict__ coefs,     // (33, 8, 32): [d*256 + s*32 + h]
    const float* __restrict__ eq_bias)
{
    __shared__ __align__(16) float  x_smT[ND * NN];   // x[d][row]  (transposed)
    __shared__ float  s_sm[ND];
    __shared__ float  base_sm[NH];
    __shared__ __align__(16) float2 A2_sm[ND * NH];   // {a,a} duplicated for f32x2
    __shared__ float  B_sm[ND * NH];                  // -> R (j)
    __shared__ float  D_sm[ND * NH];                  // -> C (k)
    __shared__ __align__(16) float  R_sm[NH * NN];    // [h*48 + j] (base folded)
    __shared__ __align__(16) float  C_sm[NH * NN];    // [h*48 + k]
    __shared__ float  part_sm[6][NH];

    const int t = threadIdx.x;
    const int b = blockIdx.y;
    const int i = blockIdx.x;

    // ---- load x transposed: x_smT[d*48 + row] ----
    for (int e = t; e < NN * ND; e += NTHREADS) {
        int d   = e / NN;
        int row = e - d * NN;
        x_smT[e] = (d < 32) ? embed[xcat[b * NN + row] * 32 + d]
                            : xfeat[b * NN + row];
    }
    __syncthreads();

    // ---- column means s_d (contiguous rows) ----
    if (t < ND) {
        const float* xr = x_smT + t * NN;
        float su = 0.f;
        #pragma unroll 8
        for (int r = 0; r < NN; r++) su += xr[r];
        s_sm[t] = su * (1.0f / 48.0f);
    }
    __syncthreads();

    // ---- per-block coefficient combos ----
    for (int e = t; e < ND * NH; e += NTHREADS) {
        int d = e >> 5;
        int h = e & 31;
        float xi = x_smT[d * NN + i];
        float s  = s_sm[d];
        const float* c = coefs + d * 256 + h;
        float a = c[0] * xi + c[32] * s;              // op0 + op1
        A2_sm[e] = make_float2(a, a);
        B_sm[e] = (c[96] * xi + c[160] * s) * s;      // op3 + op5
        D_sm[e] = (c[64] * xi + c[128] * s) * s;      // op2 + op4
    }
    if (t < NH) {
        float acc = eq_bias[t];
        for (int d = 0; d < ND; d++) {
            float xi = x_smT[d * NN + i];
            float s  = s_sm[d];
            const float* c = coefs + d * 256 + t;
            acc += (c[192] * xi + c[224] * s) * s * s;  // op6 + op7
        }
        base_sm[t] = acc;
    }
    __syncthreads();

    // ---- R[h,j] (base folded) and C[h,k] ----
    for (int e = t; e < NH * NN; e += NTHREADS) {
        int h = e / NN;
        int j = e - h * NN;
        float r  = base_sm[h];
        float cc = 0.f;
        for (int d = 0; d < ND; d++) {
            float xv = x_smT[d * NN + j];
            r  = fmaf(B_sm[d * NH + h], xv, r);
            cc = fmaf(D_sm[d * NH + h], xv, cc);
        }
        R_sm[e] = r;
        C_sm[e] = cc;
    }
    __syncthreads();

    // ---- main: per-thread tile (1 j) x (6 k) x (8 h), 2 tiles, 4 h-chunks ----
    const int lane = t & 31;
    const int warp = t >> 5;

    for (int hc = 0; hc < 4; hc++) {
        const int hc8 = hc * 8;
        float pool[8];
        #pragma unroll
        for (int hh = 0; hh < 8; hh++) pool[hh] = 0.f;

        for (int tile = 0; tile < 2; tile++) {
            int p  = t + NTHREADS * tile;       // 0..383
            int j  = p >> 3;                    // 0..47
            int k0 = (p & 7) * 6;               // 0,6,...,42

            u64 acc[8][3];
            #pragma unroll
            for (int hh = 0; hh < 8; hh++) {
                float rv = R_sm[(hc8 + hh) * NN + j];
                u64 rv2 = pack2(rv, rv);
                const u64* cp = (const u64*)(C_sm + (hc8 + hh) * NN + k0);
                #pragma unroll
                for (int q = 0; q < 3; q++)
                    acc[hh][q] = add2(rv2, cp[q]);
            }

            #pragma unroll 3
            for (int d = 0; d < ND; d++) {
                const float* xb = x_smT + d * NN;
                float xj = xb[j];
                u64 xj2 = pack2(xj, xj);
                const u64* xkp = (const u64*)(xb + k0);
                u64 pp0 = mul2(xj2, xkp[0]);
                u64 pp1 = mul2(xj2, xkp[1]);
                u64 pp2 = mul2(xj2, xkp[2]);
                const ulonglong2* A2p = (const ulonglong2*)(A2_sm + d * NH + hc8);
                #pragma unroll
                for (int h2 = 0; h2 < 4; h2++) {
                    ulonglong2 aa = A2p[h2];
                    acc[2*h2+0][0] = fma2(aa.x, pp0, acc[2*h2+0][0]);
                    acc[2*h2+0][1] = fma2(aa.x, pp1, acc[2*h2+0][1]);
                    acc[2*h2+0][2] = fma2(aa.x, pp2, acc[2*h2+0][2]);
                    acc[2*h2+1][0] = fma2(aa.y, pp0, acc[2*h2+1][0]);
                    acc[2*h2+1][1] = fma2(aa.y, pp1, acc[2*h2+1][1]);
                    acc[2*h2+1][2] = fma2(aa.y, pp2, acc[2*h2+1][2]);
                }
            }

            #pragma unroll
            for (int hh = 0; hh < 8; hh++) {
                float ss = 0.f;
                #pragma unroll
                for (int q = 0; q < 3; q++) {
                    float lo, hi;
                    unpack2(acc[hh][q], lo, hi);
                    ss += fmaxf(lo, 0.f) + fmaxf(hi, 0.f);
                }
                pool[hh] += ss;
            }
        }

        // warp reduce, lane 0 stages
        #pragma unroll
        for (int hh = 0; hh < 8; hh++) {
            float v = pool[hh];
            #pragma unroll
            for (int off = 16; off; off >>= 1)
                v += __shfl_xor_sync(0xffffffffu, v, off);
            if (lane == 0) part_sm[warp][hc8 + hh] = v;
        }
    }
    __syncthreads();

    if (t < NH) {
        float su = 0.f;
        #pragma unroll
        for (int w = 0; w < 6; w++) su += part_sm[w][t];
        g_partial[(b * NN + i) * NH + t] = su;
    }
}

// 8 blocks (one per batch row), 256 threads: coalesced reduction over i.
__global__ __launch_bounds__(256) void eq3_final(
    const float* __restrict__ out_w,
    const float* __restrict__ out_b,
    float*       __restrict__ out)
{
    __shared__ float red[8][NH];
    const int b  = blockIdx.x;
    const int t  = threadIdx.x;
    const int h  = t & 31;
    const int ig = t >> 5;          // 8 i-groups of 6

    const float* gp = g_partial + b * NN * NH;
    float su = 0.f;
    #pragma unroll
    for (int q = 0; q < 6; q++)
        su += gp[(ig * 6 + q) * NH + h];
    red[ig][h] = su;
    __syncthreads();

    if (t < NH) {
        float P = 0.f;
        #pragma unroll
        for (int g = 0; g < 8; g++) P += red[g][h];
        P *= (1.0f / 110592.0f);          // mean over n^3
        P = fmaxf(P, 0.f);
        float v = P * out_w[h];
        #pragma unroll
        for (int off = 16; off; off >>= 1)
            v += __shfl_xor_sync(0xffffffffu, v, off);
        if (h == 0) out[b] = v + out_b[0];
    }
}

extern "C" void kernel_launch(void* const* d_in, const int* in_sizes, int n_in,
                              void* d_out, int out_size)
{
    const int*   xcat    = (const int*)  d_in[0];
    const float* xfeat   = (const float*)d_in[1];
    const float* embed   = (const float*)d_in[2];
    const float* coefs   = (const float*)d_in[3];
    const float* eq_bias = (const float*)d_in[4];
    const float* out_w   = (const float*)d_in[5];
    const float* out_b   = (const float*)d_in[6];
    float* out = (float*)d_out;

    dim3 grid(NN, NB);   // (i, b)
    eq3_main<<<grid, NTHREADS>>>(xcat, xfeat, embed, coefs, eq_bias);
    eq3_final<<<NB, 256>>>(out_w, out_b, out);
}